// round 2
// baseline (speedup 1.0000x reference)
#include <cuda_runtime.h>
#include <cstdint>

#define MAXN 50000
#define FEAT 64

// ---------------- scratch (no allocations allowed) ----------------
__device__ float    g_buf[MAXN * FEAT];   // g = dinv * (x @ W)
__device__ float    g_agg[MAXN * FEAT];   // self-loop init + edge accumulation
__device__ float    g_dinv[MAXN];
__device__ int      g_cnt[MAXN];
__device__ unsigned g_gmax[192];          // order-encoded float max per column
__device__ int      g_is32;               // 1 if edge_index is int32, 0 if int64

// ---------------- helpers ----------------
__device__ __forceinline__ unsigned long long pack2(float x, float y) {
    unsigned long long u;
    asm("mov.b64 %0, {%1, %2};" : "=l"(u) : "f"(x), "f"(y));
    return u;
}
__device__ __forceinline__ void unpack2(unsigned long long u, float& x, float& y) {
    asm("mov.b64 {%0, %1}, %2;" : "=f"(x), "=f"(y) : "l"(u));
}
__device__ __forceinline__ unsigned long long ffma2(unsigned long long a,
                                                    unsigned long long b,
                                                    unsigned long long c) {
    unsigned long long d;
    asm("fma.rn.f32x2 %0, %1, %2, %3;" : "=l"(d) : "l"(a), "l"(b), "l"(c));
    return d;
}
// order-preserving float<->uint for atomicMax
__device__ __forceinline__ unsigned ford(float f) {
    unsigned u = __float_as_uint(f);
    return (u & 0x80000000u) ? ~u : (u | 0x80000000u);
}
__device__ __forceinline__ float funord(unsigned v) {
    unsigned b = (v & 0x80000000u) ? (v ^ 0x80000000u) : ~v;
    return __uint_as_float(b);
}
__device__ __forceinline__ int edge_at(const void* ei, int E, int which, int e) {
    if (g_is32) return ((const int*)ei)[(size_t)which * E + e];
    return (int)((const long long*)ei)[(size_t)which * E + e];
}

// ---------------- kernels ----------------
__global__ void init_kernel(int N) {
    int i = blockIdx.x * blockDim.x + threadIdx.x;
    if (i < N) g_cnt[i] = 0;
    if (i < 192) g_gmax[i] = 0u;
    if (i == 0) g_is32 = 0;
}

// int32-vs-int64 edge dtype detection: int64 reads of int32 data have random
// nonzero high words (indices), while genuine int64 indices are < 2^32.
__global__ void detect_kernel(const void* ei) {
    unsigned long long v = (unsigned long long)((const long long*)ei)[threadIdx.x];
    if (v >> 32) atomicOr(&g_is32, 1);
}

__global__ void count_kernel(const void* __restrict__ ei, int E) {
    int i = blockIdx.x * blockDim.x + threadIdx.x;
    if (i >= E) return;
    int d = edge_at(ei, E, 1, i);
    atomicAdd(&g_cnt[d], 1);
}

__global__ void dinv_kernel(int N) {
    int i = blockIdx.x * blockDim.x + threadIdx.x;
    if (i < N) g_dinv[i] = rsqrtf((float)(g_cnt[i] + 1));  // +1 self loop
}

// h = X @ W ; g_buf = dinv * h ; g_agg = g_buf (self-loop term)
// block: 128 threads = 4 warps; each warp owns one 16-col group (W LDS broadcast);
// each lane owns a row pair (vector LDS from transposed X tile). 64 rows/block.
__global__ __launch_bounds__(128) void gemm_kernel(
    const float* __restrict__ X, int xstride,
    const float* __restrict__ W, int nrows)
{
    __shared__ float Ws[64 * 64];      // Ws[k*64 + c]
    __shared__ float Xs[64 * 66];      // transposed: Xs[k*66 + r]
    int t = threadIdx.x;
    int row0 = blockIdx.x * 64;

    for (int i = t; i < 4096; i += 128) Ws[i] = W[i];
    for (int i = t; i < 4096; i += 128) {
        int r = i >> 6, k = i & 63;
        int gr = row0 + r;
        Xs[k * 66 + r] = (gr < nrows) ? X[(size_t)gr * xstride + k] : 0.f;
    }
    __syncthreads();

    int w = t >> 5;   // col group: cols w*16 .. w*16+15
    int l = t & 31;   // rows 2l, 2l+1

    unsigned long long acc0[8], acc1[8];
#pragma unroll
    for (int j = 0; j < 8; j++) { acc0[j] = 0ull; acc1[j] = 0ull; }

#pragma unroll 8
    for (int k = 0; k < 64; k++) {
        float2 xv = *(const float2*)&Xs[k * 66 + 2 * l];
        const float4* wp = (const float4*)&Ws[k * 64 + w * 16];
        float4 wa = wp[0], wb = wp[1], wc = wp[2], wd = wp[3];
        unsigned long long x0 = pack2(xv.x, xv.x);
        unsigned long long x1 = pack2(xv.y, xv.y);
        unsigned long long wq[8] = {
            pack2(wa.x, wa.y), pack2(wa.z, wa.w),
            pack2(wb.x, wb.y), pack2(wb.z, wb.w),
            pack2(wc.x, wc.y), pack2(wc.z, wc.w),
            pack2(wd.x, wd.y), pack2(wd.z, wd.w)};
#pragma unroll
        for (int j = 0; j < 8; j++) {
            acc0[j] = ffma2(x0, wq[j], acc0[j]);
            acc1[j] = ffma2(x1, wq[j], acc1[j]);
        }
    }

#pragma unroll
    for (int rr = 0; rr < 2; rr++) {
        int gr = row0 + 2 * l + rr;
        if (gr >= nrows) continue;
        float dv = g_dinv[gr];
        unsigned long long* acc = rr ? acc1 : acc0;
        float o[16];
#pragma unroll
        for (int j = 0; j < 8; j++) {
            unpack2(acc[j], o[2 * j], o[2 * j + 1]);
            o[2 * j] *= dv; o[2 * j + 1] *= dv;
        }
        float4* gp = (float4*)&g_buf[(size_t)gr * FEAT + w * 16];
        float4* ap = (float4*)&g_agg[(size_t)gr * FEAT + w * 16];
#pragma unroll
        for (int j = 0; j < 4; j++) {
            float4 v = make_float4(o[4 * j], o[4 * j + 1], o[4 * j + 2], o[4 * j + 3]);
            gp[j] = v; ap[j] = v;
        }
    }
}

// edge scatter: agg[dst] += g[src]; 16 threads per edge (one float4 each)
__global__ __launch_bounds__(256) void scatter_kernel(const void* __restrict__ ei, int E) {
    long long idx = (long long)blockIdx.x * blockDim.x + threadIdx.x;
    if (idx >= (long long)E * 16) return;
    int e = (int)(idx >> 4);
    int grp = (int)(idx & 15);
    int s = edge_at(ei, E, 0, e);
    int d = edge_at(ei, E, 1, e);
    float4 v = *(const float4*)&g_buf[(size_t)s * FEAT + grp * 4];
    float* p = &g_agg[(size_t)d * FEAT + grp * 4];
    asm volatile("red.global.add.v4.f32 [%0], {%1,%2,%3,%4};"
                 :: "l"(p), "f"(v.x), "f"(v.y), "f"(v.z), "f"(v.w) : "memory");
}

// out[:, colbase:colbase+64] = act(dinv * agg + b); fused column-max
__global__ __launch_bounds__(256) void finalize_kernel(
    const float* __restrict__ bias, float* __restrict__ out,
    int colbase, int dorelu, int N)
{
    int t = threadIdx.x;
    int c = t & 63, rg = t >> 6;
    float b = bias[c];
    float mx = -3.402823466e38f;
    for (int r = blockIdx.x * 4 + rg; r < N; r += gridDim.x * 4) {
        float v = g_dinv[r] * g_agg[(size_t)r * FEAT + c] + b;
        if (dorelu) v = fmaxf(v, 0.f);
        out[(size_t)r * 192 + colbase + c] = v;
        mx = fmaxf(mx, v);
    }
    __shared__ float sm[256];
    sm[t] = mx;
    __syncthreads();
    if (rg == 0) {
        mx = fmaxf(fmaxf(sm[c], sm[64 + c]), fmaxf(sm[128 + c], sm[192 + c]));
        atomicMax(&g_gmax[colbase + c], ford(mx));
    }
}

// graph_embedding + target-node logits
__global__ void tail_kernel(float* __restrict__ out,
                            const float* __restrict__ fcW,
                            const float* __restrict__ fcb,
                            const int* __restrict__ tptr, int N)
{
    int t = threadIdx.x;
    if (t < 192) out[(size_t)N * 192 + t] = funord(g_gmax[t]);
    if (t < 4) {
        int tn = *tptr;  // low 32 bits work for int32 or little-endian int64
        const float* emb = out + (size_t)tn * 192;
        float s = fcb[t];
        for (int k = 0; k < 192; k++) s += emb[k] * fcW[k * 4 + t];
        out[(size_t)N * 192 + 192 + t] = s;
    }
}

// ---------------- launch ----------------
extern "C" void kernel_launch(void* const* d_in, const int* in_sizes, int n_in,
                              void* d_out, int out_size)
{
    const float* x   = (const float*)d_in[0];
    const void*  ei  = d_in[1];
    const int*   tgt = (const int*)d_in[3];
    const float* W1  = (const float*)d_in[4];
    const float* b1  = (const float*)d_in[5];
    const float* W2  = (const float*)d_in[6];
    const float* b2  = (const float*)d_in[7];
    const float* W3  = (const float*)d_in[8];
    const float* b3  = (const float*)d_in[9];
    const float* fcW = (const float*)d_in[10];
    const float* fcb = (const float*)d_in[11];
    float* out = (float*)d_out;

    int N = in_sizes[0] / FEAT;
    int E = in_sizes[1] / 2;

    init_kernel<<<(N + 255) / 256, 256>>>(N);
    detect_kernel<<<1, 64>>>(ei);
    count_kernel<<<(E + 255) / 256, 256>>>(ei, E);
    dinv_kernel<<<(N + 255) / 256, 256>>>(N);

    const float* Wl[3] = {W1, W2, W3};
    const float* bl[3] = {b1, b2, b3};
    int gemm_blocks = (N + 63) / 64;
    long long sc_work = (long long)E * 16;
    int sc_blocks = (int)((sc_work + 255) / 256);

    for (int layer = 0; layer < 3; layer++) {
        const float* X = (layer == 0) ? x : (out + (size_t)(layer - 1) * 64);
        int stride = (layer == 0) ? FEAT : 192;
        gemm_kernel<<<gemm_blocks, 128>>>(X, stride, Wl[layer], N);
        scatter_kernel<<<sc_blocks, 256>>>(ei, E);
        finalize_kernel<<<256, 256>>>(bl[layer], out, layer * 64,
                                      (layer < 2) ? 1 : 0, N);
    }
    tail_kernel<<<1, 192>>>(out, fcW, fcb, tgt, N);
}